// round 1
// baseline (speedup 1.0000x reference)
#include <cuda_runtime.h>

// Problem constants (fixed shapes from reference):
//   B=4, S=64, F=64, V=16384, E=512, rows = B*S*F = 16384
#define V_DIM 16384
#define E_DIM 512
#define NROWS 16384

// Scratch for transposed W: Wt[v][e] so the per-row gather is contiguous.
// 16384 * 512 * 4B = 33.5 MB static device array (allocation-guard safe).
__device__ float g_Wt[(size_t)V_DIM * E_DIM];

// Transpose W [E, V] -> g_Wt [V, E] with a 32x32 shared tile.
// Grid: (V/32, E/32), block: (32, 8).
__global__ void __launch_bounds__(256) transpose_W_kernel(const float* __restrict__ W) {
    __shared__ float tile[32][33];
    const int v0 = blockIdx.x * 32;
    const int e0 = blockIdx.y * 32;
    const int tx = threadIdx.x;
    const int ty = threadIdx.y;

    // Coalesced read of W: consecutive tx -> consecutive v.
    #pragma unroll
    for (int j = 0; j < 4; j++) {
        int e = e0 + ty + j * 8;
        tile[ty + j * 8][tx] = W[(size_t)e * V_DIM + (v0 + tx)];
    }
    __syncthreads();
    // Coalesced write of Wt: consecutive tx -> consecutive e.
    #pragma unroll
    for (int j = 0; j < 4; j++) {
        int v = v0 + ty + j * 8;
        g_Wt[(size_t)v * E_DIM + (e0 + tx)] = tile[tx][ty + j * 8];
    }
}

// One block per (b,s,f) row.
// Phase A: 256 threads scan the 16384-float one-hot row (64 KB) with
//          interleaved float4 streaming loads to find the hot index.
// Phase B: write out[row, 0:512] = Wt[idx, :] + pos_emb[s, :] + fmap_emb[f, :]
__global__ void __launch_bounds__(256) combined_embedding_kernel(
    const float* __restrict__ x,
    const float* __restrict__ pos_emb,
    const float* __restrict__ fmap_emb,
    float* __restrict__ out)
{
    const int row = blockIdx.x;
    const int t = threadIdx.x;

    __shared__ int s_idx;
    if (t == 0) s_idx = 0;
    __syncthreads();

    // Interleaved float4 scan: iteration i, thread t reads elements
    // [ (i*256 + t)*4 , +4 ). 16 iterations cover V=16384.
    const float4* xr = reinterpret_cast<const float4*>(x + (size_t)row * V_DIM);
    int found = -1;
    #pragma unroll
    for (int i = 0; i < 16; i++) {
        float4 v = __ldcs(&xr[i * 256 + t]);   // streaming: don't pollute L2
        int base = (i * 256 + t) * 4;
        if (v.x != 0.0f) found = base + 0;
        if (v.y != 0.0f) found = base + 1;
        if (v.z != 0.0f) found = base + 2;
        if (v.w != 0.0f) found = base + 3;
    }
    // Exactly one thread in the block finds the one-hot position.
    if (found >= 0) s_idx = found;
    __syncthreads();

    const int idx = s_idx;
    const int s = (row >> 6) & 63;   // row = ((b*64)+s)*64 + f
    const int f = row & 63;

    const float* wt = g_Wt + (size_t)idx * E_DIM;
    const float* pe = pos_emb + (size_t)s * E_DIM;
    const float* fe = fmap_emb + (size_t)f * E_DIM;
    float* o = out + (size_t)row * E_DIM;

    // E=512, 256 threads -> 2 elements per thread, fully coalesced.
    o[t]       = wt[t]       + __ldg(&pe[t])       + __ldg(&fe[t]);
    o[t + 256] = wt[t + 256] + __ldg(&pe[t + 256]) + __ldg(&fe[t + 256]);
}

extern "C" void kernel_launch(void* const* d_in, const int* in_sizes, int n_in,
                              void* d_out, int out_size) {
    const float* x        = (const float*)d_in[0];  // [4,64,64,16384]
    const float* W        = (const float*)d_in[1];  // [512,16384]
    const float* pos_emb  = (const float*)d_in[2];  // [256,512]
    const float* fmap_emb = (const float*)d_in[3];  // [256,512]
    float* out = (float*)d_out;                     // [4,64,64,512]

    (void)in_sizes; (void)n_in; (void)out_size;

    dim3 tb(32, 8);
    dim3 tg(V_DIM / 32, E_DIM / 32);
    transpose_W_kernel<<<tg, tb>>>(W);

    combined_embedding_kernel<<<NROWS, 256>>>(x, pos_emb, fmap_emb, out);
}

// round 2
// speedup vs baseline: 1.6540x; 1.6540x over previous
#include <cuda_runtime.h>

// Problem constants (fixed shapes from reference):
//   B=4, S=64, F=64, V=16384, E=512, rows = B*S*F = 16384
#define V_DIM 16384
#define E_DIM 512
#define NROWS 16384

// One block per (b,s,f) row.
// Phase A: early-exit scan of the 16384-float one-hot row in chunks of 2048
//          elements (256 threads x 2 float4, MLP=2). Expected 4.5/8 chunks read.
// Phase B: out[row, :] = W[:, idx] + pos_emb[s, :] + fmap_emb[f, :]
//          W gathered column-wise directly; sector amplification absorbed by L2
//          (W = 33.5 MB fits; x stream is __ldcs evict-first so it persists).
__global__ void __launch_bounds__(256) combined_embedding_kernel(
    const float* __restrict__ x,
    const float* __restrict__ W,
    const float* __restrict__ pos_emb,
    const float* __restrict__ fmap_emb,
    float* __restrict__ out)
{
    const int row = blockIdx.x;
    const int t = threadIdx.x;

    __shared__ int s_idx;
    if (t == 0) s_idx = -1;
    __syncthreads();

    const float4* xr = reinterpret_cast<const float4*>(x + (size_t)row * V_DIM);

    // 8 chunks of 2048 elements. Chunk c: thread t reads float4s
    // [c*512 + t] and [c*512 + 256 + t]  (elements c*2048 .. c*2048+2047).
    #pragma unroll 1
    for (int c = 0; c < 8; c++) {
        const int q0 = c * 512 + t;
        const int q1 = q0 + 256;
        float4 a = __ldcs(&xr[q0]);   // streaming: don't pollute L2 (protects W)
        float4 b = __ldcs(&xr[q1]);

        int found = -1;
        int base0 = q0 * 4;
        if (a.x != 0.0f) found = base0 + 0;
        if (a.y != 0.0f) found = base0 + 1;
        if (a.z != 0.0f) found = base0 + 2;
        if (a.w != 0.0f) found = base0 + 3;
        int base1 = q1 * 4;
        if (b.x != 0.0f) found = base1 + 0;
        if (b.y != 0.0f) found = base1 + 1;
        if (b.z != 0.0f) found = base1 + 2;
        if (b.w != 0.0f) found = base1 + 3;

        if (found >= 0) s_idx = found;   // exactly one thread ever writes
        __syncthreads();
        if (s_idx >= 0) break;
        // (no second barrier needed: s_idx only transitions -1 -> value, and
        //  the next writer writes the same kind of value after the next loads)
    }

    const int idx = (s_idx >= 0) ? s_idx : 0;
    const int s = (row >> 6) & 63;   // row = ((b*64)+s)*64 + f
    const int f = row & 63;

    const float* pe = pos_emb + (size_t)s * E_DIM;
    const float* fe = fmap_emb + (size_t)f * E_DIM;
    float* o = out + (size_t)row * E_DIM;

    // E=512, 256 threads -> 2 elements each. W gather: column idx, stride V.
    const int e0 = t;
    const int e1 = t + 256;
    float w0 = __ldg(&W[(size_t)e0 * V_DIM + idx]);
    float w1 = __ldg(&W[(size_t)e1 * V_DIM + idx]);
    o[e0] = w0 + __ldg(&pe[e0]) + __ldg(&fe[e0]);
    o[e1] = w1 + __ldg(&pe[e1]) + __ldg(&fe[e1]);
}

extern "C" void kernel_launch(void* const* d_in, const int* in_sizes, int n_in,
                              void* d_out, int out_size) {
    const float* x        = (const float*)d_in[0];  // [4,64,64,16384]
    const float* W        = (const float*)d_in[1];  // [512,16384]
    const float* pos_emb  = (const float*)d_in[2];  // [256,512]
    const float* fmap_emb = (const float*)d_in[3];  // [256,512]
    float* out = (float*)d_out;                     // [4,64,64,512]

    (void)in_sizes; (void)n_in; (void)out_size;

    combined_embedding_kernel<<<NROWS, 256>>>(x, W, pos_emb, fmap_emb, out);
}